// round 2
// baseline (speedup 1.0000x reference)
#include <cuda_runtime.h>
#include <cuda_bf16.h>

// GCN: out = spmm(A, relu(spmm(A, x@W1)+b1) @ W2) + b2
// N=50000, E=1.6M, 512 -> 128 -> 64, all fp32.
// NOTE: edge_index is int32 on device (JAX default config downcasts int64).

#define IN_DIM  512
#define HID_DIM 128
#define OUT_DIM 64
#define N_MAX   50000

// Scratch (allocation-free rule: __device__ globals)
__device__ float g_S1[(size_t)N_MAX * HID_DIM];  // x @ W1
__device__ float g_H [(size_t)N_MAX * HID_DIM];  // spmm1 accumulator (+b1)
__device__ float g_S2[(size_t)N_MAX * OUT_DIM];  // relu(H) @ W2

// ---------------------------------------------------------------------------
// Vectorized fp32 reduction to global: 4 floats per op, no return trip.
// ---------------------------------------------------------------------------
__device__ __forceinline__ void red_add_v4(float* addr, float4 v) {
    asm volatile("red.global.add.v4.f32 [%0], {%1, %2, %3, %4};"
                 :: "l"(addr), "f"(v.x), "f"(v.y), "f"(v.z), "f"(v.w)
                 : "memory");
}

// ---------------------------------------------------------------------------
// Tiled fp32 GEMM: C[M, BN] = A[M, K] @ B[K, BN].  BN == full matrix N.
// Optional ReLU applied to A elements on load (for layer-2 fusion).
// ---------------------------------------------------------------------------
template<int BM, int BN, int BK, int TM, int TN, bool RELU>
__global__ void gemm_kernel(const float* __restrict__ A,
                            const float* __restrict__ B,
                            float* __restrict__ C, int M, int K) {
    constexpr int THREADS = (BM / TM) * (BN / TN);
    __shared__ float As[BM][BK];
    __shared__ float Bs[BK][BN];

    const int tid  = threadIdx.x;
    const int tcol = tid % (BN / TN);   // column group
    const int trow = tid / (BN / TN);   // row group
    const int rowBase = blockIdx.x * BM;

    float acc[TM][TN];
    #pragma unroll
    for (int i = 0; i < TM; i++)
        #pragma unroll
        for (int j = 0; j < TN; j++) acc[i][j] = 0.f;

    for (int k0 = 0; k0 < K; k0 += BK) {
        // --- load A tile (BM x BK) as float4s, zero-pad M tail ---
        constexpr int A4 = BM * BK / 4;
        #pragma unroll
        for (int f = tid; f < A4; f += THREADS) {
            int r  = f / (BK / 4);
            int kq = f % (BK / 4);
            int grow = rowBase + r;
            float4 v = make_float4(0.f, 0.f, 0.f, 0.f);
            if (grow < M)
                v = *(const float4*)(A + (size_t)grow * K + k0 + kq * 4);
            if (RELU) {
                v.x = fmaxf(v.x, 0.f); v.y = fmaxf(v.y, 0.f);
                v.z = fmaxf(v.z, 0.f); v.w = fmaxf(v.w, 0.f);
            }
            *(float4*)&As[r][kq * 4] = v;
        }
        // --- load B tile (BK x BN) ---
        constexpr int B4 = BK * BN / 4;
        #pragma unroll
        for (int f = tid; f < B4; f += THREADS) {
            int kk = f / (BN / 4);
            int c4 = f % (BN / 4);
            *(float4*)&Bs[kk][c4 * 4] =
                *(const float4*)(B + (size_t)(k0 + kk) * BN + c4 * 4);
        }
        __syncthreads();

        #pragma unroll
        for (int kk = 0; kk < BK; kk++) {
            float a[TM];
            #pragma unroll
            for (int i = 0; i < TM; i++) a[i] = As[trow * TM + i][kk];  // broadcast
            float4 b = *(const float4*)&Bs[kk][tcol * TN];
            #pragma unroll
            for (int i = 0; i < TM; i++) {
                acc[i][0] = fmaf(a[i], b.x, acc[i][0]);
                acc[i][1] = fmaf(a[i], b.y, acc[i][1]);
                acc[i][2] = fmaf(a[i], b.z, acc[i][2]);
                acc[i][3] = fmaf(a[i], b.w, acc[i][3]);
            }
        }
        __syncthreads();
    }

    #pragma unroll
    for (int i = 0; i < TM; i++) {
        int grow = rowBase + trow * TM + i;
        if (grow < M) {
            float4 v = make_float4(acc[i][0], acc[i][1], acc[i][2], acc[i][3]);
            *(float4*)(C + (size_t)grow * BN + tcol * TN) = v;
        }
    }
}

// ---------------------------------------------------------------------------
// Broadcast bias into the accumulator buffer: dst[i] = b[i & (D-1)]
// ---------------------------------------------------------------------------
__global__ void init_bias_kernel(float* __restrict__ dst,
                                 const float* __restrict__ b,
                                 int dmask, long long total) {
    long long i = (long long)blockIdx.x * blockDim.x + threadIdx.x;
    if (i < total) dst[i] = b[(int)(i & dmask)];
}

// ---------------------------------------------------------------------------
// Edge-parallel SpMM: dst[row] += w * src[col], D = CH*4 floats per row.
// One float4 chunk per thread; CH consecutive threads share one edge
// (uniform broadcast loads of row/col/w).
// ---------------------------------------------------------------------------
template<int CH>
__global__ void spmm_kernel(const int* __restrict__ rows,
                            const int* __restrict__ cols,
                            const float* __restrict__ ew,
                            const float* __restrict__ src,
                            float* dst, int E) {
    long long t = (long long)blockIdx.x * blockDim.x + threadIdx.x;
    int e = (int)(t >> (CH == 32 ? 5 : 4));
    int c = (int)(t & (CH - 1));
    if (e >= E) return;
    const int D = CH * 4;
    int r  = rows[e];
    int cl = cols[e];
    float w = ew[e];
    float4 v = *(const float4*)(src + (size_t)cl * D + c * 4);
    float4 m = make_float4(v.x * w, v.y * w, v.z * w, v.w * w);
    red_add_v4(dst + (size_t)r * D + c * 4, m);
}

// ---------------------------------------------------------------------------
extern "C" void kernel_launch(void* const* d_in, const int* in_sizes, int n_in,
                              void* d_out, int out_size) {
    const float* x  = (const float*)d_in[0];
    const int*   ei = (const int*)d_in[1];     // [2, E] int32 (JAX x64 disabled)
    const float* ew = (const float*)d_in[2];
    const float* W1 = (const float*)d_in[3];
    const float* b1 = (const float*)d_in[4];
    const float* W2 = (const float*)d_in[5];
    const float* b2 = (const float*)d_in[6];
    float* out = (float*)d_out;

    const int M = in_sizes[0] / IN_DIM;   // 50000
    const int E = in_sizes[2];            // 1600000

    float *S1, *H, *S2;
    cudaGetSymbolAddress((void**)&S1, g_S1);
    cudaGetSymbolAddress((void**)&H,  g_H);
    cudaGetSymbolAddress((void**)&S2, g_S2);

    const int* e_rows = ei;
    const int* e_cols = ei + E;

    // 1) S1 = x @ W1
    gemm_kernel<64, HID_DIM, 16, 8, 4, false>
        <<<(M + 63) / 64, (64 / 8) * (HID_DIM / 4)>>>(x, W1, S1, M, IN_DIM);

    // 2) H = broadcast(b1)
    {
        long long total = (long long)M * HID_DIM;
        init_bias_kernel<<<(unsigned)((total + 255) / 256), 256>>>(H, b1, HID_DIM - 1, total);
    }

    // 3) H += A @ S1  (edge-parallel, red.v4)
    {
        long long T = (long long)E * (HID_DIM / 4);
        spmm_kernel<HID_DIM / 4><<<(unsigned)((T + 255) / 256), 256>>>(
            e_rows, e_cols, ew, S1, H, E);
    }

    // 4) S2 = relu(H) @ W2
    gemm_kernel<64, OUT_DIM, 16, 8, 4, true>
        <<<(M + 63) / 64, (64 / 8) * (OUT_DIM / 4)>>>(H, W2, S2, M, HID_DIM);

    // 5) out = broadcast(b2)
    {
        long long total = (long long)M * OUT_DIM;
        init_bias_kernel<<<(unsigned)((total + 255) / 256), 256>>>(out, b2, OUT_DIM - 1, total);
    }

    // 6) out += A @ S2
    {
        long long T = (long long)E * (OUT_DIM / 4);
        spmm_kernel<OUT_DIM / 4><<<(unsigned)((T + 255) / 256), 256>>>(
            e_rows, e_cols, ew, S2, out, E);
    }
}